// round 15
// baseline (speedup 1.0000x reference)
#include <cuda_runtime.h>
#include <math.h>

#define B_ 32
#define P_ 24564
#define O_ 16
#define C_ 81
#define ROWS_ 128   // priors per phaseA block
#define CAP_ 8192   // phaseB candidate cap (smem)

// ---- scratch (device globals; no allocation) ----
__device__ float  g_bto[B_ * P_];     // best truth overlap per prior
__device__ int    g_bti[B_ * P_];     // best truth idx per prior
__device__ __align__(16) float g_min_c[B_ * P_];  // mining values (class CE)
__device__ __align__(16) float g_min_o[B_ * P_];  // mining values (obj CE)
__device__ unsigned long long g_key[B_ * O_];     // per-truth best prior key
__device__ double g_dacc[3];          // [0]=loss_l [1]=loss_c [2]=loss_obj
__device__ int    g_npos[B_];
__device__ int    g_npos_tot;
__device__ int    g_ktot;

__global__ void k_init() {
    int t = threadIdx.x;
    if (t < 3)  g_dacc[t] = 0.0;
    if (t < B_) g_npos[t] = 0;
    if (t == 0) { g_npos_tot = 0; g_ktot = 0; }
    if (t < B_ * O_) g_key[t] = 0ULL;
}

// Deterministic fp32 IoU — identical expression everywhere it is evaluated.
__device__ __forceinline__ float iou_f(
    float px1, float py1, float px2, float py2, float parea,
    float tx1, float ty1, float tx2, float ty2, float tarea)
{
    float ix1 = fmaxf(tx1, px1), iy1 = fmaxf(ty1, py1);
    float ix2 = fminf(tx2, px2), iy2 = fminf(ty2, py2);
    float iw = fmaxf(__fsub_rn(ix2, ix1), 0.f);
    float ih = fmaxf(__fsub_rn(iy2, iy1), 0.f);
    float inter = __fmul_rn(iw, ih);
    float denom = __fsub_rn(__fadd_rn(tarea, parea), inter);
    return __fdiv_rn(inter, denom);
}

// ---- M1+M2 fused: per-prior argmax over truths AND per-truth argmax over priors
__global__ void k_iou_max(const float* __restrict__ priors,
                          const float* __restrict__ truths) {
    const int b = blockIdx.y;
    const int tid = threadIdx.x;
    const int lane = tid & 31, wid = tid >> 5;
    const int p = blockIdx.x * 256 + tid;
    const bool valid = (p < P_);

    __shared__ float tx1[O_], ty1[O_], tx2[O_], ty2[O_], tarea[O_];
    __shared__ unsigned long long s_key[8][O_];
    if (tid < O_) {
        const float* t = truths + ((size_t)b * O_ + tid) * 4;
        tx1[tid] = t[0]; ty1[tid] = t[1];
        tx2[tid] = t[2]; ty2[tid] = t[3];
        tarea[tid] = __fmul_rn(__fsub_rn(t[2], t[0]), __fsub_rn(t[3], t[1]));
    }
    __syncthreads();

    unsigned long long key[O_];
    float bv = -1.f; int bo = 0;
    if (valid) {
        const float* pr = priors + (size_t)p * 4;
        float cx = pr[0], cy = pr[1], w = pr[2], h = pr[3];
        float hw = __fmul_rn(w, 0.5f), hh = __fmul_rn(h, 0.5f);
        float px1 = __fsub_rn(cx, hw), py1 = __fsub_rn(cy, hh);
        float px2 = __fadd_rn(cx, hw), py2 = __fadd_rn(cy, hh);
        float parea = __fmul_rn(__fsub_rn(px2, px1), __fsub_rn(py2, py1));
#pragma unroll
        for (int o = 0; o < O_; o++) {
            float v = iou_f(px1, py1, px2, py2, parea,
                            tx1[o], ty1[o], tx2[o], ty2[o], tarea[o]);
            if (v > bv) { bv = v; bo = o; }  // strict > keeps FIRST max (o asc)
            key[o] = ((unsigned long long)__float_as_uint(v) << 32)
                   | (unsigned long long)(0xFFFFFFFFu - (unsigned)p);
        }
        size_t idx = (size_t)b * P_ + p;
        g_bto[idx] = bv; g_bti[idx] = bo;
    } else {
#pragma unroll
        for (int o = 0; o < O_; o++) key[o] = 0ULL;
    }

#pragma unroll
    for (int o = 0; o < O_; o++) {
        unsigned long long kk = key[o];
#pragma unroll
        for (int s = 16; s; s >>= 1) {
            unsigned long long other = __shfl_xor_sync(0xffffffffu, kk, s);
            if (other > kk) kk = other;
        }
        if (lane == 0) s_key[wid][o] = kk;
    }
    __syncthreads();
    if (tid < O_) {
        unsigned long long m = s_key[0][tid];
#pragma unroll
        for (int w = 1; w < 8; w++)
            if (s_key[w][tid] > m) m = s_key[w][tid];
        atomicMax(&g_key[b * O_ + tid], m);
    }
}

__device__ __forceinline__ float sl1(float d) {
    float ax = fabsf(d);
    return ax < 1.f ? 0.5f * ax * ax : ax - 0.5f;
}

// ---- phase A: thread-per-prior CE via smem-staged tiles; conf_t fused in ----
__global__ void __launch_bounds__(ROWS_) k_phaseA(
        const float* __restrict__ loc,
        const float* __restrict__ conf,
        const float* __restrict__ obj,
        const float* __restrict__ priors,
        const float* __restrict__ truths,
        const int* __restrict__ labels) {
    const int b = blockIdx.y;
    const int tid = threadIdx.x;
    const int base = blockIdx.x * ROWS_;
    const int rows = (P_ - base < ROWS_) ? (P_ - base) : ROWS_;

    __shared__ float tile[ROWS_ * C_];         // 41472 B
    __shared__ int   s_bp[O_], s_lab[O_];
    __shared__ double s_ll, s_pc, s_po;
    __shared__ int s_np;

    if (tid == 0) { s_ll = 0.0; s_pc = 0.0; s_po = 0.0; s_np = 0; }
    if (tid < O_) {
        s_bp[tid]  = (int)(0xFFFFFFFFu - (unsigned)(g_key[b * O_ + tid] & 0xFFFFFFFFu));
        s_lab[tid] = labels[b * O_ + tid];
    }

    {
        const float4* src = reinterpret_cast<const float4*>(
            conf + ((size_t)b * P_ + base) * (size_t)C_);
        float4* dst = reinterpret_cast<float4*>(tile);
        const int n4 = rows * C_ / 4;
        for (int i = tid; i < n4; i += ROWS_) dst[i] = src[i];
    }
    __syncthreads();

    double a_ll = 0.0, a_pc = 0.0, a_po = 0.0; int a_np = 0;

    if (tid < rows) {
        const int p = base + tid;
        const size_t idx = (size_t)b * P_ + p;
        const float* r = tile + tid * C_;

        float s0 = 0.f, s1 = 0.f, s2 = 0.f, s3 = 0.f;
#pragma unroll
        for (int i = 0; i < 80; i += 4) {
            s0 += __expf(r[i]);
            s1 += __expf(r[i + 1]);
            s2 += __expf(r[i + 2]);
            s3 += __expf(r[i + 3]);
        }
        s0 += __expf(r[80]);
        float lse = __logf((s0 + s1) + (s2 + s3));

        float v = g_bto[idx];
        int ti = g_bti[idx];
        bool ov = false;
#pragma unroll
        for (int o = 0; o < O_; o++)
            if (s_bp[o] == p) { ti = o; ov = true; }
        int t = (ov || v >= 0.5f) ? s_lab[ti] : 0;

        float cec = lse - r[t];
        g_min_c[idx] = (t > 0) ? 0.f : cec;

        const float2 ob = *reinterpret_cast<const float2*>(obj + idx * 2);
        float mo = fmaxf(ob.x, ob.y);
        float lse2 = mo + __logf(__expf(ob.x - mo) + __expf(ob.y - mo));
        float ceo = lse2 - ((t > 0) ? ob.y : ob.x);
        g_min_o[idx] = (t > 0) ? 0.f : ceo;

        if (t > 0) {
            a_pc = (double)cec; a_po = (double)ceo; a_np = 1;
            const float* tr = truths + ((size_t)b * O_ + ti) * 4;
            float mx1 = tr[0], my1 = tr[1], mx2 = tr[2], my2 = tr[3];
            const float* pr = priors + (size_t)p * 4;
            float gx = ((mx1 + mx2) * 0.5f - pr[0]) / (0.1f * pr[2]);
            float gy = ((my1 + my2) * 0.5f - pr[1]) / (0.1f * pr[3]);
            float gw = __logf((mx2 - mx1) / pr[2]) / 0.2f;
            float gh = __logf((my2 - my1) / pr[3]) / 0.2f;
            const float* ld = loc + idx * 4;
            a_ll = (double)(sl1(ld[0] - gx) + sl1(ld[1] - gy)
                          + sl1(ld[2] - gw) + sl1(ld[3] - gh));
        }
    }

    unsigned any = __ballot_sync(0xffffffffu, a_np != 0);
    if (any) {
#pragma unroll
        for (int s = 16; s; s >>= 1) {
            a_ll += __shfl_xor_sync(0xffffffffu, a_ll, s);
            a_pc += __shfl_xor_sync(0xffffffffu, a_pc, s);
            a_po += __shfl_xor_sync(0xffffffffu, a_po, s);
            a_np += __shfl_xor_sync(0xffffffffu, a_np, s);
        }
        if ((tid & 31) == 0) {
            atomicAdd(&s_ll, a_ll); atomicAdd(&s_pc, a_pc);
            atomicAdd(&s_po, a_po); atomicAdd(&s_np, a_np);
        }
    }
    __syncthreads();
    if (tid == 0 && s_np) {
        atomicAdd(&g_dacc[0], s_ll);
        atomicAdd(&g_dacc[1], s_pc);
        atomicAdd(&g_dacc[2], s_po);
        atomicAdd(&g_npos[b], s_np);
        atomicAdd(&g_npos_tot, s_np);
    }
}

// Parallel suffix-selection over an nb-bin histogram (warp 0 only).
__device__ __forceinline__ void select_bin(const unsigned* hist, int nb, int kk,
                                           int tid, int* sh_bin, int* sh_kk) {
    if (tid < 32) {
        const int seg = nb >> 5;
        const int b0 = tid * seg;
        int segsum = 0;
        for (int j = 0; j < seg; j++) segsum += (int)hist[b0 + j];
        int SI = segsum;
#pragma unroll
        for (int s = 1; s < 32; s <<= 1) {
            int v2 = __shfl_down_sync(0xffffffffu, SI, s);
            if (tid + s < 32) SI += v2;
        }
        int SI_above = SI - segsum;
        if (SI >= kk && SI_above < kk) {
            int c = kk - SI_above;
            for (int j = seg - 1; j >= 0; j--) {
                int h = (int)hist[b0 + j];
                if (c <= h) { *sh_bin = b0 + j; *sh_kk = c; break; }
                c -= h;
            }
        }
    }
}

// ---- phase B: top-k sum. Level-1 radix on bits[21:32), then candidate
//      compaction to smem; levels 2+3 run in-smem. One block per (batch,array).
__global__ void __launch_bounds__(1024) k_phaseB() {
    const int b = blockIdx.x;
    const int arr = blockIdx.y;
    const int tid = threadIdx.x;
    const int NT = 1024;
    const int N4 = P_ / 4;              // 6141

    __shared__ unsigned hist[2048];
    __shared__ unsigned cand[CAP_];
    __shared__ int s_nc;
    __shared__ double s_above, s_res;
    __shared__ double wsum[32];
    __shared__ int sh_bin, sh_kk;

    int k = g_npos[b] * 3;
    if (k > P_ - 1) k = P_ - 1;

    const float* vals = (arr == 0 ? g_min_c : g_min_o) + (size_t)b * P_;
    const float4* v4 = reinterpret_cast<const float4*>(vals);

    double result = 0.0;
    if (k > 0) {
        // ---- level 1: histogram on bits [21,32) ----
        hist[tid] = 0; hist[tid + 1024] = 0;
        if (tid == 0) { s_nc = 0; s_above = 0.0; s_res = 0.0; }
        __syncthreads();
        for (int i = tid; i < N4; i += NT) {
            float4 q = v4[i];
#pragma unroll
            for (int c4 = 0; c4 < 4; c4++) {
                float f = (c4 == 0) ? q.x : (c4 == 1) ? q.y : (c4 == 2) ? q.z : q.w;
                int bin = __float_as_uint(f) >> 21;
                unsigned mm = __match_any_sync(__activemask(), bin);
                if ((tid & 31) == (__ffs(mm) - 1))
                    atomicAdd(&hist[bin], __popc(mm));
            }
        }
        __syncthreads();
        select_bin(hist, 2048, k, tid, &sh_bin, &sh_kk);
        __syncthreads();
        const unsigned prefix11 = (unsigned)sh_bin;
        int kk = sh_kk;
        __syncthreads();

        // ---- pass 2: compact candidates (top bits == prefix11) + sum above-bin ----
        double above = 0.0;
        for (int i = tid; i < N4; i += NT) {
            float4 q = v4[i];
#pragma unroll
            for (int c4 = 0; c4 < 4; c4++) {
                float f = (c4 == 0) ? q.x : (c4 == 1) ? q.y : (c4 == 2) ? q.z : q.w;
                unsigned v = __float_as_uint(f);
                unsigned h = v >> 21;
                if (h > prefix11) above += (double)f;
                else if (h == prefix11) {
                    int pos = atomicAdd(&s_nc, 1);
                    if (pos < CAP_) cand[pos] = v;
                }
            }
        }
        if (above != 0.0) atomicAdd(&s_above, above);
        __syncthreads();
        const int nc_raw = s_nc;
        unsigned T;                       // final 32-bit threshold

        if (nc_raw <= CAP_) {
            const int nc = nc_raw;
            // ---- level 2 (smem): bits [10,21) ----
            hist[tid] = 0; hist[tid + 1024] = 0;
            __syncthreads();
            for (int j = tid; j < nc; j += NT)
                atomicAdd(&hist[(cand[j] >> 10) & 2047], 1u);
            __syncthreads();
            select_bin(hist, 2048, kk, tid, &sh_bin, &sh_kk);
            __syncthreads();
            const unsigned pref22 = (prefix11 << 11) | (unsigned)sh_bin;  // bits [10,32)
            kk = sh_kk;
            __syncthreads();
            // ---- level 3 (smem): bits [0,10) ----
            if (tid < 1024) hist[tid] = 0;
            __syncthreads();
            for (int j = tid; j < nc; j += NT) {
                unsigned v = cand[j];
                if ((v >> 10) == pref22) atomicAdd(&hist[v & 1023], 1u);
            }
            __syncthreads();
            select_bin(hist, 1024, kk, tid, &sh_bin, &sh_kk);
            __syncthreads();
            T = (pref22 << 10) | (unsigned)sh_bin;
            kk = sh_kk;

            // sum candidates strictly above T
            double loc = 0.0;
            for (int j = tid; j < nc; j += NT) {
                unsigned v = cand[j];
                if (v > T) loc += (double)__uint_as_float(v);
            }
#pragma unroll
            for (int o = 16; o; o >>= 1) loc += __shfl_xor_sync(0xffffffffu, loc, o);
            if ((tid & 31) == 0) wsum[tid >> 5] = loc;
            __syncthreads();
            if (tid < 32) {
                double v = wsum[tid];
#pragma unroll
                for (int o = 16; o; o >>= 1) v += __shfl_xor_sync(0xffffffffu, v, o);
                if (tid == 0)
                    s_res = v + (double)kk * (double)__uint_as_float(T);
            }
            __syncthreads();
            result = s_above + s_res;
        } else {
            // ---- fallback: global rescans for levels 2 and 3 (rare) ----
            unsigned prefix = prefix11 << 21;
            for (int L = 0; L < 2; L++) {
                const int lo = (L == 0) ? 10 : 0;
                const int hi = (L == 0) ? 21 : 10;
                const int nb = (L == 0) ? 2048 : 1024;
                for (int i = tid; i < nb; i += NT) hist[i] = 0;
                __syncthreads();
                for (int i = tid; i < N4; i += NT) {
                    float4 q = v4[i];
#pragma unroll
                    for (int c4 = 0; c4 < 4; c4++) {
                        float f = (c4 == 0) ? q.x : (c4 == 1) ? q.y : (c4 == 2) ? q.z : q.w;
                        unsigned v = __float_as_uint(f);
                        if ((v >> hi) == (prefix >> hi)) {
                            int bin = (v >> lo) & (nb - 1);
                            unsigned mm = __match_any_sync(__activemask(), bin);
                            if ((tid & 31) == (__ffs(mm) - 1))
                                atomicAdd(&hist[bin], __popc(mm));
                        }
                    }
                }
                __syncthreads();
                select_bin(hist, nb, kk, tid, &sh_bin, &sh_kk);
                __syncthreads();
                prefix |= ((unsigned)sh_bin) << lo;
                kk = sh_kk;
                __syncthreads();
            }
            T = prefix;
            double loc = 0.0;
            for (int i = tid; i < N4; i += NT) {
                float4 q = v4[i];
#pragma unroll
                for (int c4 = 0; c4 < 4; c4++) {
                    float f = (c4 == 0) ? q.x : (c4 == 1) ? q.y : (c4 == 2) ? q.z : q.w;
                    if (__float_as_uint(f) > T) loc += (double)f;
                }
            }
#pragma unroll
            for (int o = 16; o; o >>= 1) loc += __shfl_xor_sync(0xffffffffu, loc, o);
            if ((tid & 31) == 0) wsum[tid >> 5] = loc;
            __syncthreads();
            if (tid < 32) {
                double v = wsum[tid];
#pragma unroll
                for (int o = 16; o; o >>= 1) v += __shfl_xor_sync(0xffffffffu, v, o);
                if (tid == 0)
                    s_res = v + (double)kk * (double)__uint_as_float(T);
            }
            __syncthreads();
            result = s_res;
        }
    }

    if (tid == 0) {
        if (k > 0) atomicAdd(&g_dacc[arr == 0 ? 1 : 2], result);
        if (arr == 0) atomicAdd(&g_ktot, k);
    }
}

__global__ void k_final(float* __restrict__ out) {
    double N  = (double)(g_npos_tot > 1 ? g_npos_tot : 1);
    double N1 = (double)(g_ktot > 1 ? g_ktot : 1);
    out[0] = (float)(g_dacc[0] / N);
    out[1] = (float)(g_dacc[1] / N);
    out[2] = (float)(0.4 * g_dacc[2] / N1);
}

extern "C" void kernel_launch(void* const* d_in, const int* in_sizes, int n_in,
                              void* d_out, int out_size) {
    const float* loc    = (const float*)d_in[0];
    const float* conf   = (const float*)d_in[1];
    const float* obj    = (const float*)d_in[2];
    const float* priors = (const float*)d_in[3];
    const float* truths = (const float*)d_in[4];
    const int*   labels = (const int*)d_in[5];   // int32 (jax x64 disabled)

    k_init<<<1, 512>>>();
    k_iou_max<<<dim3((P_ + 255) / 256, B_), 256>>>(priors, truths);
    k_phaseA<<<dim3((P_ + ROWS_ - 1) / ROWS_, B_), ROWS_>>>(loc, conf, obj,
                                                            priors, truths, labels);
    k_phaseB<<<dim3(B_, 2), 1024>>>();
    k_final<<<1, 1>>>((float*)d_out);
}

// round 16
// speedup vs baseline: 2.1788x; 2.1788x over previous
#include <cuda_runtime.h>
#include <math.h>

#define B_ 32
#define P_ 24564
#define O_ 16
#define C_ 81
#define ROWS_ 128    // priors per phaseA block
#define NB1_ 4096    // level-1 bins (12 bits: v >> 20)
#define CAP_ 6144    // phaseB candidate cap (smem)

// ---- scratch (device globals; no allocation) ----
__device__ float  g_bto[B_ * P_];
__device__ int    g_bti[B_ * P_];
__device__ __align__(16) float g_min_c[B_ * P_];
__device__ __align__(16) float g_min_o[B_ * P_];
__device__ unsigned g_hist[B_ * 2 * NB1_];        // level-1 histograms (1 MB)
__device__ unsigned long long g_key[B_ * O_];
__device__ double g_dacc[3];
__device__ int    g_npos[B_];
__device__ int    g_npos_tot;
__device__ int    g_ktot;

__global__ void k_init() {
    int i = blockIdx.x * 256 + threadIdx.x;
    if (i < B_ * 2 * NB1_) g_hist[i] = 0;
    if (i < B_ * O_) g_key[i] = 0ULL;
    if (i < 3)  g_dacc[i] = 0.0;
    if (i < B_) g_npos[i] = 0;
    if (i == 0) { g_npos_tot = 0; g_ktot = 0; }
}

__device__ __forceinline__ float iou_f(
    float px1, float py1, float px2, float py2, float parea,
    float tx1, float ty1, float tx2, float ty2, float tarea)
{
    float ix1 = fmaxf(tx1, px1), iy1 = fmaxf(ty1, py1);
    float ix2 = fminf(tx2, px2), iy2 = fminf(ty2, py2);
    float iw = fmaxf(__fsub_rn(ix2, ix1), 0.f);
    float ih = fmaxf(__fsub_rn(iy2, iy1), 0.f);
    float inter = __fmul_rn(iw, ih);
    float denom = __fsub_rn(__fadd_rn(tarea, parea), inter);
    return __fdiv_rn(inter, denom);
}

// ---- M1+M2 fused: per-prior argmax over truths AND per-truth argmax over priors
__global__ void k_iou_max(const float* __restrict__ priors,
                          const float* __restrict__ truths) {
    const int b = blockIdx.y;
    const int tid = threadIdx.x;
    const int lane = tid & 31, wid = tid >> 5;
    const int p = blockIdx.x * 256 + tid;
    const bool valid = (p < P_);

    __shared__ float tx1[O_], ty1[O_], tx2[O_], ty2[O_], tarea[O_];
    __shared__ unsigned long long s_key[8][O_];
    if (tid < O_) {
        const float* t = truths + ((size_t)b * O_ + tid) * 4;
        tx1[tid] = t[0]; ty1[tid] = t[1];
        tx2[tid] = t[2]; ty2[tid] = t[3];
        tarea[tid] = __fmul_rn(__fsub_rn(t[2], t[0]), __fsub_rn(t[3], t[1]));
    }
    __syncthreads();

    unsigned long long key[O_];
    float bv = -1.f; int bo = 0;
    if (valid) {
        const float* pr = priors + (size_t)p * 4;
        float cx = pr[0], cy = pr[1], w = pr[2], h = pr[3];
        float hw = __fmul_rn(w, 0.5f), hh = __fmul_rn(h, 0.5f);
        float px1 = __fsub_rn(cx, hw), py1 = __fsub_rn(cy, hh);
        float px2 = __fadd_rn(cx, hw), py2 = __fadd_rn(cy, hh);
        float parea = __fmul_rn(__fsub_rn(px2, px1), __fsub_rn(py2, py1));
#pragma unroll
        for (int o = 0; o < O_; o++) {
            float v = iou_f(px1, py1, px2, py2, parea,
                            tx1[o], ty1[o], tx2[o], ty2[o], tarea[o]);
            if (v > bv) { bv = v; bo = o; }  // strict > keeps FIRST max (o asc)
            key[o] = ((unsigned long long)__float_as_uint(v) << 32)
                   | (unsigned long long)(0xFFFFFFFFu - (unsigned)p);
        }
        size_t idx = (size_t)b * P_ + p;
        g_bto[idx] = bv; g_bti[idx] = bo;
    } else {
#pragma unroll
        for (int o = 0; o < O_; o++) key[o] = 0ULL;
    }

#pragma unroll
    for (int o = 0; o < O_; o++) {
        unsigned long long kk = key[o];
#pragma unroll
        for (int s = 16; s; s >>= 1) {
            unsigned long long other = __shfl_xor_sync(0xffffffffu, kk, s);
            if (other > kk) kk = other;
        }
        if (lane == 0) s_key[wid][o] = kk;
    }
    __syncthreads();
    if (tid < O_) {
        unsigned long long m = s_key[0][tid];
#pragma unroll
        for (int w = 1; w < 8; w++)
            if (s_key[w][tid] > m) m = s_key[w][tid];
        atomicMax(&g_key[b * O_ + tid], m);
    }
}

__device__ __forceinline__ float sl1(float d) {
    float ax = fabsf(d);
    return ax < 1.f ? 0.5f * ax * ax : ax - 0.5f;
}

// ---- phase A: thread-per-prior CE via smem-staged tiles; conf_t fused;
//      ALSO builds the level-1 mining histograms (warp-aggregated global RED).
__global__ void __launch_bounds__(ROWS_) k_phaseA(
        const float* __restrict__ loc,
        const float* __restrict__ conf,
        const float* __restrict__ obj,
        const float* __restrict__ priors,
        const float* __restrict__ truths,
        const int* __restrict__ labels) {
    const int b = blockIdx.y;
    const int tid = threadIdx.x;
    const int base = blockIdx.x * ROWS_;
    const int rows = (P_ - base < ROWS_) ? (P_ - base) : ROWS_;

    __shared__ float tile[ROWS_ * C_];         // 41472 B
    __shared__ int   s_bp[O_], s_lab[O_];
    __shared__ double s_ll, s_pc, s_po;
    __shared__ int s_np;

    if (tid == 0) { s_ll = 0.0; s_pc = 0.0; s_po = 0.0; s_np = 0; }
    if (tid < O_) {
        s_bp[tid]  = (int)(0xFFFFFFFFu - (unsigned)(g_key[b * O_ + tid] & 0xFFFFFFFFu));
        s_lab[tid] = labels[b * O_ + tid];
    }

    {
        const float4* src = reinterpret_cast<const float4*>(
            conf + ((size_t)b * P_ + base) * (size_t)C_);
        float4* dst = reinterpret_cast<float4*>(tile);
        const int n4 = rows * C_ / 4;
        for (int i = tid; i < n4; i += ROWS_) dst[i] = src[i];
    }
    __syncthreads();

    double a_ll = 0.0, a_pc = 0.0, a_po = 0.0; int a_np = 0;

    if (tid < rows) {
        const int p = base + tid;
        const size_t idx = (size_t)b * P_ + p;
        const float* r = tile + tid * C_;

        float s0 = 0.f, s1 = 0.f, s2 = 0.f, s3 = 0.f;
#pragma unroll
        for (int i = 0; i < 80; i += 4) {
            s0 += __expf(r[i]);
            s1 += __expf(r[i + 1]);
            s2 += __expf(r[i + 2]);
            s3 += __expf(r[i + 3]);
        }
        s0 += __expf(r[80]);
        float lse = __logf((s0 + s1) + (s2 + s3));

        float v = g_bto[idx];
        int ti = g_bti[idx];
        bool ov = false;
#pragma unroll
        for (int o = 0; o < O_; o++)
            if (s_bp[o] == p) { ti = o; ov = true; }
        int t = (ov || v >= 0.5f) ? s_lab[ti] : 0;

        float cec = lse - r[t];
        float mcv = (t > 0) ? 0.f : cec;
        g_min_c[idx] = mcv;

        const float2 ob = *reinterpret_cast<const float2*>(obj + idx * 2);
        float mo = fmaxf(ob.x, ob.y);
        float lse2 = mo + __logf(__expf(ob.x - mo) + __expf(ob.y - mo));
        float ceo = lse2 - ((t > 0) ? ob.y : ob.x);
        float mov = (t > 0) ? 0.f : ceo;
        g_min_o[idx] = mov;

        // level-1 histogram updates (12-bit bins), warp-aggregated
        {
            unsigned act = __activemask();
            unsigned bc = __float_as_uint(mcv) >> 20;
            unsigned mm = __match_any_sync(act, bc);
            if ((tid & 31) == (__ffs(mm) - 1))
                atomicAdd(&g_hist[((unsigned)(b * 2) << 12) + bc], __popc(mm));
            unsigned bo2 = __float_as_uint(mov) >> 20;
            mm = __match_any_sync(act, bo2);
            if ((tid & 31) == (__ffs(mm) - 1))
                atomicAdd(&g_hist[((unsigned)(b * 2 + 1) << 12) + bo2], __popc(mm));
        }

        if (t > 0) {
            a_pc = (double)cec; a_po = (double)ceo; a_np = 1;
            const float* tr = truths + ((size_t)b * O_ + ti) * 4;
            float mx1 = tr[0], my1 = tr[1], mx2 = tr[2], my2 = tr[3];
            const float* pr = priors + (size_t)p * 4;
            float gx = ((mx1 + mx2) * 0.5f - pr[0]) / (0.1f * pr[2]);
            float gy = ((my1 + my2) * 0.5f - pr[1]) / (0.1f * pr[3]);
            float gw = __logf((mx2 - mx1) / pr[2]) / 0.2f;
            float gh = __logf((my2 - my1) / pr[3]) / 0.2f;
            const float* ld = loc + idx * 4;
            a_ll = (double)(sl1(ld[0] - gx) + sl1(ld[1] - gy)
                          + sl1(ld[2] - gw) + sl1(ld[3] - gh));
        }
    }

    unsigned any = __ballot_sync(0xffffffffu, a_np != 0);
    if (any) {
#pragma unroll
        for (int s = 16; s; s >>= 1) {
            a_ll += __shfl_xor_sync(0xffffffffu, a_ll, s);
            a_pc += __shfl_xor_sync(0xffffffffu, a_pc, s);
            a_po += __shfl_xor_sync(0xffffffffu, a_po, s);
            a_np += __shfl_xor_sync(0xffffffffu, a_np, s);
        }
        if ((tid & 31) == 0) {
            atomicAdd(&s_ll, a_ll); atomicAdd(&s_pc, a_pc);
            atomicAdd(&s_po, a_po); atomicAdd(&s_np, a_np);
        }
    }
    __syncthreads();
    if (tid == 0 && s_np) {
        atomicAdd(&g_dacc[0], s_ll);
        atomicAdd(&g_dacc[1], s_pc);
        atomicAdd(&g_dacc[2], s_po);
        atomicAdd(&g_npos[b], s_np);
        atomicAdd(&g_npos_tot, s_np);
    }
}

// Parallel suffix-selection over an nb-bin smem histogram (warp 0 only).
__device__ __forceinline__ void select_bin(const unsigned* hist, int nb, int kk,
                                           int tid, int* sh_bin, int* sh_kk) {
    if (tid < 32) {
        const int seg = nb >> 5;
        const int b0 = tid * seg;
        int segsum = 0;
        for (int j = 0; j < seg; j++) segsum += (int)hist[b0 + j];
        int SI = segsum;
#pragma unroll
        for (int s = 1; s < 32; s <<= 1) {
            int v2 = __shfl_down_sync(0xffffffffu, SI, s);
            if (tid + s < 32) SI += v2;
        }
        int SI_above = SI - segsum;
        if (SI >= kk && SI_above < kk) {
            int c = kk - SI_above;
            for (int j = seg - 1; j >= 0; j--) {
                int h = (int)hist[b0 + j];
                if (c <= h) { *sh_bin = b0 + j; *sh_kk = c; break; }
                c -= h;
            }
        }
    }
}

// ---- phase B: top-k sum using the PREBUILT level-1 histogram (from phaseA).
//      One global pass (above-sum + compaction), then in-smem refinement.
__global__ void __launch_bounds__(1024) k_phaseB() {
    const int b = blockIdx.x;
    const int arr = blockIdx.y;
    const int tid = threadIdx.x;
    const int NT = 1024;
    const int N4 = P_ / 4;              // 6141

    __shared__ unsigned hist[NB1_];     // 16 KB (selection + refine reuse)
    __shared__ unsigned cand[CAP_];     // 24 KB
    __shared__ int s_nc;
    __shared__ double s_above, s_res;
    __shared__ double wsum[32];
    __shared__ int sh_bin, sh_kk;

    int k = g_npos[b] * 3;
    if (k > P_ - 1) k = P_ - 1;

    const float* vals = (arr == 0 ? g_min_c : g_min_o) + (size_t)b * P_;
    const float4* v4 = reinterpret_cast<const float4*>(vals);

    double result = 0.0;
    if (k > 0) {
        // load prebuilt level-1 histogram
        const unsigned* gh = g_hist + ((unsigned)(b * 2 + arr) << 12);
        for (int i = tid; i < NB1_; i += NT) hist[i] = gh[i];
        if (tid == 0) { s_nc = 0; s_above = 0.0; s_res = 0.0; }
        __syncthreads();

        select_bin(hist, NB1_, k, tid, &sh_bin, &sh_kk);
        __syncthreads();
        const unsigned bin1 = (unsigned)sh_bin;
        int kk = sh_kk;
        const int nc = (int)hist[bin1];
        __syncthreads();

        unsigned T;
        if (nc <= CAP_) {
            // ---- single global pass: above-bin sum + compact in-bin ----
            double above = 0.0;
            for (int i = tid; i < N4; i += NT) {
                float4 q = v4[i];
#pragma unroll
                for (int c4 = 0; c4 < 4; c4++) {
                    float f = (c4 == 0) ? q.x : (c4 == 1) ? q.y : (c4 == 2) ? q.z : q.w;
                    unsigned v = __float_as_uint(f);
                    unsigned h = v >> 20;
                    if (h > bin1) above += (double)f;
                    else if (h == bin1) cand[atomicAdd(&s_nc, 1)] = v;
                }
            }
#pragma unroll
            for (int o = 16; o; o >>= 1) above += __shfl_xor_sync(0xffffffffu, above, o);
            if ((tid & 31) == 0 && above != 0.0) atomicAdd(&s_above, above);
            __syncthreads();

            // ---- refine level 2 (smem): bits [10,20) ----
            if (tid < 1024) hist[tid] = 0;
            __syncthreads();
            for (int j = tid; j < nc; j += NT)
                atomicAdd(&hist[(cand[j] >> 10) & 1023], 1u);
            __syncthreads();
            select_bin(hist, 1024, kk, tid, &sh_bin, &sh_kk);
            __syncthreads();
            const unsigned pref22 = (bin1 << 10) | (unsigned)sh_bin;  // bits [10,32)
            kk = sh_kk;
            __syncthreads();
            // ---- refine level 3 (smem): bits [0,10) ----
            if (tid < 1024) hist[tid] = 0;
            __syncthreads();
            for (int j = tid; j < nc; j += NT) {
                unsigned v = cand[j];
                if ((v >> 10) == pref22) atomicAdd(&hist[v & 1023], 1u);
            }
            __syncthreads();
            select_bin(hist, 1024, kk, tid, &sh_bin, &sh_kk);
            __syncthreads();
            T = (pref22 << 10) | (unsigned)sh_bin;
            kk = sh_kk;

            // sum candidates strictly above T
            double loc = 0.0;
            for (int j = tid; j < nc; j += NT) {
                unsigned v = cand[j];
                if (v > T) loc += (double)__uint_as_float(v);
            }
#pragma unroll
            for (int o = 16; o; o >>= 1) loc += __shfl_xor_sync(0xffffffffu, loc, o);
            if ((tid & 31) == 0) wsum[tid >> 5] = loc;
            __syncthreads();
            if (tid < 32) {
                double v = wsum[tid];
#pragma unroll
                for (int o = 16; o; o >>= 1) v += __shfl_xor_sync(0xffffffffu, v, o);
                if (tid == 0)
                    s_res = v + (double)kk * (double)__uint_as_float(T);
            }
            __syncthreads();
            result = s_above + s_res;
        } else {
            // ---- fallback: global refinement passes (rare) ----
            unsigned prefix = bin1 << 20;
            for (int L = 0; L < 2; L++) {
                const int lo = (L == 0) ? 10 : 0;
                const int hi = (L == 0) ? 20 : 10;
                for (int i = tid; i < 1024; i += NT) hist[i] = 0;
                __syncthreads();
                for (int i = tid; i < N4; i += NT) {
                    float4 q = v4[i];
#pragma unroll
                    for (int c4 = 0; c4 < 4; c4++) {
                        float f = (c4 == 0) ? q.x : (c4 == 1) ? q.y : (c4 == 2) ? q.z : q.w;
                        unsigned v = __float_as_uint(f);
                        if ((v >> hi) == (prefix >> hi)) {
                            int bn = (v >> lo) & 1023;
                            unsigned mm = __match_any_sync(__activemask(), bn);
                            if ((tid & 31) == (__ffs(mm) - 1))
                                atomicAdd(&hist[bn], __popc(mm));
                        }
                    }
                }
                __syncthreads();
                select_bin(hist, 1024, kk, tid, &sh_bin, &sh_kk);
                __syncthreads();
                prefix |= ((unsigned)sh_bin) << lo;
                kk = sh_kk;
                __syncthreads();
            }
            T = prefix;
            double loc = 0.0;
            for (int i = tid; i < N4; i += NT) {
                float4 q = v4[i];
#pragma unroll
                for (int c4 = 0; c4 < 4; c4++) {
                    float f = (c4 == 0) ? q.x : (c4 == 1) ? q.y : (c4 == 2) ? q.z : q.w;
                    if (__float_as_uint(f) > T) loc += (double)f;
                }
            }
#pragma unroll
            for (int o = 16; o; o >>= 1) loc += __shfl_xor_sync(0xffffffffu, loc, o);
            if ((tid & 31) == 0) wsum[tid >> 5] = loc;
            __syncthreads();
            if (tid < 32) {
                double v = wsum[tid];
#pragma unroll
                for (int o = 16; o; o >>= 1) v += __shfl_xor_sync(0xffffffffu, v, o);
                if (tid == 0)
                    s_res = v + (double)kk * (double)__uint_as_float(T);
            }
            __syncthreads();
            result = s_res;
        }
    }

    if (tid == 0) {
        if (k > 0) atomicAdd(&g_dacc[arr == 0 ? 1 : 2], result);
        if (arr == 0) atomicAdd(&g_ktot, k);
    }
}

__global__ void k_final(float* __restrict__ out) {
    double N  = (double)(g_npos_tot > 1 ? g_npos_tot : 1);
    double N1 = (double)(g_ktot > 1 ? g_ktot : 1);
    out[0] = (float)(g_dacc[0] / N);
    out[1] = (float)(g_dacc[1] / N);
    out[2] = (float)(0.4 * g_dacc[2] / N1);
}

extern "C" void kernel_launch(void* const* d_in, const int* in_sizes, int n_in,
                              void* d_out, int out_size) {
    const float* loc    = (const float*)d_in[0];
    const float* conf   = (const float*)d_in[1];
    const float* obj    = (const float*)d_in[2];
    const float* priors = (const float*)d_in[3];
    const float* truths = (const float*)d_in[4];
    const int*   labels = (const int*)d_in[5];   // int32 (jax x64 disabled)

    k_init<<<(B_ * 2 * NB1_ + 255) / 256, 256>>>();
    k_iou_max<<<dim3((P_ + 255) / 256, B_), 256>>>(priors, truths);
    k_phaseA<<<dim3((P_ + ROWS_ - 1) / ROWS_, B_), ROWS_>>>(loc, conf, obj,
                                                            priors, truths, labels);
    k_phaseB<<<dim3(B_, 2), 1024>>>();
    k_final<<<1, 1>>>((float*)d_out);
}